// round 1
// baseline (speedup 1.0000x reference)
#include <cuda_runtime.h>
#include <stdint.h>

// Problem constants (static graph dims)
#define BTOT    16384
#define IN_DIM  512
#define NHID    128
#define NOUT    256
#define TB      32          // batch rows per block (== warp size: lane = row)
#define NTHREADS 512        // 16 warps
#define NWARPS  16

// Conflict-free smem strides (odd / co-prime with 32)
#define XS_STRIDE 513
#define HS_STRIDE 129
#define OS_STRIDE 257

#define EH_CAP 4096
#define EO_CAP 8192

// Packed static edge tables (built by prep kernel each launch; deterministic)
__device__ int2 g_eh[EH_CAP];        // {col | act<<16, weight-as-int}
__device__ int2 g_eo[EO_CAP];
__device__ int  g_hptr[NHID + 1];
__device__ int  g_optr[NOUT + 1];

// ---------------- fast math helpers (ex2/rcp approx: rel err ~1e-6) ---------
__device__ __forceinline__ float ex2f(float x) {
    float r; asm("ex2.approx.ftz.f32 %0, %1;" : "=f"(r) : "f"(x)); return r;
}
__device__ __forceinline__ float rcpf(float x) {
    float r; asm("rcp.approx.ftz.f32 %0, %1;" : "=f"(r) : "f"(x)); return r;
}
__device__ __forceinline__ float tanh_fast(float z) {
    // tanh(z) = (e^{2z} - 1) / (e^{2z} + 1), e^{2z} = 2^{2z*log2(e)}
    float t = fminf(fmaxf(2.885390082f * z, -126.f), 126.f);
    float e = ex2f(t);
    return (e - 1.f) * rcpf(e + 1.f);
}
__device__ __forceinline__ float sig_fast(float z) {
    // sigmoid(z) = 1 / (1 + 2^{-z*log2(e)})
    float t = fminf(fmaxf(-1.442695041f * z, -126.f), 126.f);
    return rcpf(1.f + ex2f(t));
}

// act is warp-uniform (all lanes share the edge) -> uniform branches, no divergence
__device__ __forceinline__ float edge_val(float xv, int2 e) {
    float w = __int_as_float(e.y);
    int   a = e.x >> 16;
    float z = xv * w;
    if (a == 1) return z;
    if (a == 3) return fmaxf(z, 0.f);
    if (a == 2) return tanh_fast(z);
    return sig_fast(z);                 // a == 4
}

// ---------------- prep: pack edges + CSR row pointers -----------------------
__device__ __forceinline__ int lower_bound_dev(const int* a, int n, int v) {
    int lo = 0, hi = n;
    while (lo < hi) { int m = (lo + hi) >> 1; if (a[m] < v) lo = m + 1; else hi = m; }
    return lo;
}

__global__ void prep_kernel(const float* __restrict__ wh, const float* __restrict__ wo,
                            const int* __restrict__ rows_h, const int* __restrict__ cols_h,
                            const int* __restrict__ acts_h,
                            const int* __restrict__ rows_o, const int* __restrict__ cols_o,
                            const int* __restrict__ acts_o,
                            int Eh, int Eo) {
    int t = threadIdx.x, nt = blockDim.x;
    if (Eh > EH_CAP) Eh = EH_CAP;
    if (Eo > EO_CAP) Eo = EO_CAP;
    for (int e = t; e < Eh; e += nt)
        g_eh[e] = make_int2(cols_h[e] | (acts_h[e] << 16), __float_as_int(wh[e]));
    for (int e = t; e < Eo; e += nt)
        g_eo[e] = make_int2(cols_o[e] | (acts_o[e] << 16), __float_as_int(wo[e]));
    for (int r = t; r <= NHID; r += nt)
        g_hptr[r] = lower_bound_dev(rows_h, Eh, r);
    for (int r = t; r <= NOUT; r += nt)
        g_optr[r] = lower_bound_dev(rows_o, Eo, r);
}

// ---------------- main kernel ----------------------------------------------
// Block handles TB=32 batch rows. lane = batch row within tile, warp = node.
// All memory access patterns conflict-free; edge metadata warp-uniform.
__global__ __launch_bounds__(NTHREADS, 1)
void wann_kernel(const float* __restrict__ x, float* __restrict__ out) {
    extern __shared__ float sm[];
    float* xs   = sm;                                   // [TB][XS_STRIDE]
    float* Hs   = xs + TB * XS_STRIDE;                  // [TB][HS_STRIDE]
    float* outs = Hs + TB * HS_STRIDE;                  // [TB][OS_STRIDE]

    const int tid  = threadIdx.x;
    const int warp = tid >> 5;
    const int lane = tid & 31;
    const int row0 = blockIdx.x * TB;

    // ---- Phase 0: stage x tile into smem (coalesced float4 loads) ----
    {
        const float4* x4 = (const float4*)(x + (size_t)row0 * IN_DIM);
        // 32 rows * 128 float4 = 4096 float4
        #pragma unroll
        for (int i = 0; i < (TB * IN_DIM / 4) / NTHREADS; i++) {
            int t  = tid + i * NTHREADS;
            int r  = t >> 7;            // /128
            int c4 = t & 127;
            float4 v = x4[r * 128 + c4];
            float* dst = xs + r * XS_STRIDE + c4 * 4;
            dst[0] = v.x; dst[1] = v.y; dst[2] = v.z; dst[3] = v.w;
        }
    }
    __syncthreads();

    // ---- Phase 1: hidden nodes. warp -> node, lane -> batch row ----
    const float* xrow = xs + lane * XS_STRIDE;
    for (int h = warp; h < NHID; h += NWARPS) {
        int b0 = g_hptr[h], b1 = g_hptr[h + 1];
        float a0 = 0.f, a1 = 0.f;
        int i = b0;
        for (; i + 1 < b1; i += 2) {
            int2 e0 = __ldg(&g_eh[i]);
            int2 e1 = __ldg(&g_eh[i + 1]);
            a0 += edge_val(xrow[e0.x & 0xFFFF], e0);
            a1 += edge_val(xrow[e1.x & 0xFFFF], e1);
        }
        if (i < b1) {
            int2 e0 = __ldg(&g_eh[i]);
            a0 += edge_val(xrow[e0.x & 0xFFFF], e0);
        }
        Hs[lane * HS_STRIDE + h] = a0 + a1;
    }
    __syncthreads();

    // ---- Phase 2: output nodes ----
    const float* hrow = Hs + lane * HS_STRIDE;
    for (int o = warp; o < NOUT; o += NWARPS) {
        int b0 = g_optr[o], b1 = g_optr[o + 1];
        float a0 = 0.f, a1 = 0.f;
        int i = b0;
        for (; i + 1 < b1; i += 2) {
            int2 e0 = __ldg(&g_eo[i]);
            int2 e1 = __ldg(&g_eo[i + 1]);
            int c0 = e0.x & 0xFFFF;
            int c1 = e1.x & 0xFFFF;
            float s0 = (c0 < IN_DIM) ? xrow[c0] : hrow[c0 - IN_DIM];
            float s1 = (c1 < IN_DIM) ? xrow[c1] : hrow[c1 - IN_DIM];
            a0 += edge_val(s0, e0);
            a1 += edge_val(s1, e1);
        }
        if (i < b1) {
            int2 e0 = __ldg(&g_eo[i]);
            int c0 = e0.x & 0xFFFF;
            float s0 = (c0 < IN_DIM) ? xrow[c0] : hrow[c0 - IN_DIM];
            a0 += edge_val(s0, e0);
        }
        outs[lane * OS_STRIDE + o] = tanh_fast(a0 + a1);
    }
    __syncthreads();

    // ---- Phase 3: coalesced flush of output tile ----
    {
        float* orow = out + (size_t)row0 * NOUT;
        #pragma unroll
        for (int i = 0; i < (TB * NOUT) / NTHREADS; i++) {
            int t = tid + i * NTHREADS;
            int r = t >> 8;             // /256
            int c = t & 255;
            orow[r * NOUT + c] = outs[r * OS_STRIDE + c];
        }
    }
}

// ---------------- launch ----------------------------------------------------
extern "C" void kernel_launch(void* const* d_in, const int* in_sizes, int n_in,
                              void* d_out, int out_size) {
    const float* x      = (const float*)d_in[0];
    const float* wh     = (const float*)d_in[1];
    const float* wo     = (const float*)d_in[2];
    const int*   rows_h = (const int*)d_in[3];
    const int*   cols_h = (const int*)d_in[4];
    const int*   acts_h = (const int*)d_in[5];
    const int*   rows_o = (const int*)d_in[6];
    const int*   cols_o = (const int*)d_in[7];
    const int*   acts_o = (const int*)d_in[8];
    float*       out    = (float*)d_out;

    int Eh = in_sizes[1];
    int Eo = in_sizes[2];

    prep_kernel<<<1, 512>>>(wh, wo, rows_h, cols_h, acts_h, rows_o, cols_o, acts_o, Eh, Eo);

    size_t smem = (size_t)(TB * XS_STRIDE + TB * HS_STRIDE + TB * OS_STRIDE) * sizeof(float);
    cudaFuncSetAttribute(wann_kernel, cudaFuncAttributeMaxDynamicSharedMemorySize, (int)smem);
    wann_kernel<<<BTOT / TB, NTHREADS, smem>>>(x, out);
}

// round 6
// speedup vs baseline: 1.1938x; 1.1938x over previous
#include <cuda_runtime.h>
#include <stdint.h>

// Static graph dims
#define BTOT     16384
#define IN_DIM   512
#define NHID     128
#define NOUT     256
#define TB       32          // batch rows per block; lane = row
#define NTHREADS 512
#define NWARPS   16

#define LB_STRIDE 641        // 512 x + 128 H + 1 pad (odd -> conflict-free)
#define OS_STRIDE 257

#define EH_CAP 4096
#define EO_CAP 8192

// Edge tables, grouped per node in order [linear, relu, tanh, sigmoid],
// with activation constants pre-folded into the weights.
// e.x = source column (0..639), e.y = weight bits.
__device__ int2 g_eh[EH_CAP];
__device__ int2 g_eo[EO_CAP];
// Segment starts: node n group g (g=0 lin,1 relu,2 tanh,3 sig) at seg[4n+g]; seg[4N]=E.
__device__ __align__(16) int g_hseg[4 * NHID + 4];
__device__ __align__(16) int g_oseg[4 * NOUT + 4];

// ---------------- fast math ----------------
__device__ __forceinline__ float ex2f(float x) {
    float r; asm("ex2.approx.ftz.f32 %0, %1;" : "=f"(r) : "f"(x)); return r;
}
__device__ __forceinline__ float rcpf(float x) {
    float r; asm("rcp.approx.ftz.f32 %0, %1;" : "=f"(r) : "f"(x)); return r;
}
// tanh(z) with t = 2*log2(e)*z already applied
__device__ __forceinline__ float tanh_from_t(float t) {
    float e = ex2f(fminf(t, 126.f));      // t->-inf: e->0 -> result -1 (correct)
    return (e - 1.f) * rcpf(e + 1.f);
}

// ---------------- prep: CSR + act-grouped packing ----------------
__device__ __forceinline__ int lower_bound_dev(const int* a, int n, int v) {
    int lo = 0, hi = n;
    while (lo < hi) { int m = (lo + hi) >> 1; if (a[m] < v) lo = m + 1; else hi = m; }
    return lo;
}

// Group order MUST match node_accum: g0=act1(linear), g1=act3(relu),
// g2=act2(tanh, w *= 2*log2e), g3=act4(sigmoid, w *= -log2e).
__device__ __constant__ int c_act_order[4] = {1, 3, 2, 4};

__global__ void prep_kernel(const float* __restrict__ wh, const float* __restrict__ wo,
                            const int* __restrict__ rows_h, const int* __restrict__ cols_h,
                            const int* __restrict__ acts_h,
                            const int* __restrict__ rows_o, const int* __restrict__ cols_o,
                            const int* __restrict__ acts_o,
                            int Eh, int Eo) {
    __shared__ int hptr[NHID + 1];
    __shared__ int optr[NOUT + 1];
    int t = threadIdx.x;
    if (Eh > EH_CAP) Eh = EH_CAP;
    if (Eo > EO_CAP) Eo = EO_CAP;

    for (int r = t; r <= NHID; r += NTHREADS) hptr[r] = lower_bound_dev(rows_h, Eh, r);
    for (int r = t; r <= NOUT; r += NTHREADS) optr[r] = lower_bound_dev(rows_o, Eo, r);
    __syncthreads();

    for (int h = t; h < NHID; h += NTHREADS) {
        int b0 = hptr[h], b1 = hptr[h + 1];
        int pos = b0;
        #pragma unroll
        for (int g = 0; g < 4; g++) {
            int a = c_act_order[g];
            g_hseg[4 * h + g] = pos;
            for (int i = b0; i < b1; i++) {
                if (acts_h[i] == a) {
                    float w = wh[i];
                    if (a == 2)      w *= 2.885390082f;    // 2*log2(e)
                    else if (a == 4) w *= -1.442695041f;   // -log2(e)
                    g_eh[pos++] = make_int2(cols_h[i], __float_as_int(w));
                }
            }
        }
    }
    for (int o = t; o < NOUT; o += NTHREADS) {
        int b0 = optr[o], b1 = optr[o + 1];
        int pos = b0;
        #pragma unroll
        for (int g = 0; g < 4; g++) {
            int a = c_act_order[g];
            g_oseg[4 * o + g] = pos;
            for (int i = b0; i < b1; i++) {
                if (acts_o[i] == a) {
                    float w = wo[i];
                    if (a == 2)      w *= 2.885390082f;
                    else if (a == 4) w *= -1.442695041f;
                    g_eo[pos++] = make_int2(cols_o[i], __float_as_int(w));
                }
            }
        }
    }
    if (t == 0) { g_hseg[4 * NHID] = Eh; g_oseg[4 * NOUT] = Eo; }
}

// ---------------- per-node accumulation over act-sorted segments ------------
// Segments: [p0,p1) linear, [p1,p2) relu, [p2,p3) tanh(folded), [p3,p4) sigmoid(folded)
__device__ __forceinline__ float node_accum(const float* __restrict__ lrow,
                                            const int2* __restrict__ edges,
                                            int p0, int p1, int p2, int p3, int p4) {
    float a0 = 0.f, a1 = 0.f;
    #pragma unroll 4
    for (int i = p0; i < p1; i++) {                       // linear: pure FFMA
        int2 e = __ldg(&edges[i]);
        a0 = fmaf(lrow[e.x], __int_as_float(e.y), a0);
    }
    #pragma unroll 4
    for (int i = p1; i < p2; i++) {                       // relu
        int2 e = __ldg(&edges[i]);
        a1 += fmaxf(lrow[e.x] * __int_as_float(e.y), 0.f);
    }
    #pragma unroll 2
    for (int i = p2; i < p3; i++) {                       // tanh (w pre-scaled 2*log2e)
        int2 e = __ldg(&edges[i]);
        float ee = ex2f(fminf(lrow[e.x] * __int_as_float(e.y), 126.f));
        a0 += (ee - 1.f) * rcpf(ee + 1.f);
    }
    #pragma unroll 2
    for (int i = p3; i < p4; i++) {                       // sigmoid (w pre-scaled -log2e)
        int2 e = __ldg(&edges[i]);
        a1 += rcpf(1.f + ex2f(lrow[e.x] * __int_as_float(e.y)));
    }
    return a0 + a1;
}

// ---------------- main kernel ----------------
__global__ __launch_bounds__(NTHREADS, 2)
void wann_kernel(const float* __restrict__ x, float* __restrict__ out) {
    extern __shared__ float sm[];
    float* lb = sm;                         // [TB][LB_STRIDE]: x | H per lane-row

    const int tid  = threadIdx.x;
    const int warp = tid >> 5;
    const int lane = tid & 31;
    const int row0 = blockIdx.x * TB;

    // Phase 0: stage x tile (coalesced float4 global loads)
    {
        const float4* x4 = (const float4*)(x + (size_t)row0 * IN_DIM);
        #pragma unroll
        for (int i = 0; i < (TB * IN_DIM / 4) / NTHREADS; i++) {
            int t  = tid + i * NTHREADS;
            int r  = t >> 7;
            int c4 = t & 127;
            float4 v = x4[r * 128 + c4];
            float* d = lb + r * LB_STRIDE + c4 * 4;
            d[0] = v.x; d[1] = v.y; d[2] = v.z; d[3] = v.w;
        }
    }
    __syncthreads();

    float* lrow = lb + lane * LB_STRIDE;

    // Phase 1: hidden nodes (warp -> node, lane -> batch row); H into lane row
    #pragma unroll
    for (int j = 0; j < NHID / NWARPS; j++) {
        int h = warp + j * NWARPS;
        int4 s = *(const int4*)&g_hseg[4 * h];
        int  s4 = g_hseg[4 * h + 4];
        lrow[IN_DIM + h] = node_accum(lrow, g_eh, s.x, s.y, s.z, s.w, s4);
    }
    __syncthreads();

    // Phase 2: output nodes -> registers (16 per thread)
    float val[NOUT / NWARPS];
    #pragma unroll
    for (int j = 0; j < NOUT / NWARPS; j++) {
        int o = warp + j * NWARPS;
        int4 s = *(const int4*)&g_oseg[4 * o];
        int  s4 = g_oseg[4 * o + 4];
        float acc = node_accum(lrow, g_eo, s.x, s.y, s.z, s.w, s4);
        val[j] = tanh_from_t(2.885390082f * acc);   // output activation
    }
    __syncthreads();    // all reads of lb done -> safe to reuse as out staging

    // Phase 3a: stage outputs into reused smem [TB][OS_STRIDE]
    #pragma unroll
    for (int j = 0; j < NOUT / NWARPS; j++) {
        int o = warp + j * NWARPS;
        lb[lane * OS_STRIDE + o] = val[j];
    }
    __syncthreads();

    // Phase 3b: coalesced flush
    {
        float* orow = out + (size_t)row0 * NOUT;
        #pragma unroll
        for (int i = 0; i < (TB * NOUT) / NTHREADS; i++) {
            int t = tid + i * NTHREADS;
            int r = t >> 8;
            int c = t & 255;
            orow[r * NOUT + c] = lb[r * OS_STRIDE + c];
        }
    }
}

// ---------------- launch ----------------
extern "C" void kernel_launch(void* const* d_in, const int* in_sizes, int n_in,
                              void* d_out, int out_size) {
    const float* x      = (const float*)d_in[0];
    const float* wh     = (const float*)d_in[1];
    const float* wo     = (const float*)d_in[2];
    const int*   rows_h = (const int*)d_in[3];
    const int*   cols_h = (const int*)d_in[4];
    const int*   acts_h = (const int*)d_in[5];
    const int*   rows_o = (const int*)d_in[6];
    const int*   cols_o = (const int*)d_in[7];
    const int*   acts_o = (const int*)d_in[8];
    float*       out    = (float*)d_out;

    int Eh = in_sizes[1];
    int Eo = in_sizes[2];

    prep_kernel<<<1, NTHREADS>>>(wh, wo, rows_h, cols_h, acts_h,
                                 rows_o, cols_o, acts_o, Eh, Eo);

    size_t smem = (size_t)(TB * LB_STRIDE) * sizeof(float);   // 82 KB -> 2 blocks/SM
    cudaFuncSetAttribute(wann_kernel, cudaFuncAttributeMaxDynamicSharedMemorySize, (int)smem);
    wann_kernel<<<BTOT / TB, NTHREADS, smem>>>(x, out);
}

// round 11
// speedup vs baseline: 1.3160x; 1.1023x over previous
#include <cuda_runtime.h>
#include <stdint.h>

// Static graph dims
#define BTOT     16384
#define IN_DIM   512
#define NHID     128
#define NOUT     256
#define TB       64          // batch rows per block; thread handles rows lane, lane+32
#define NTHREADS 1024
#define NWARPS   32

#define LB_STRIDE 641        // 512 x + 128 H + 1 pad (odd -> conflict-free)
#define OS_STRIDE 257

#define EH_CAP 4096
#define EO_CAP 8192

// Edge tables, grouped per node in order [linear, relu, tanh, sigmoid],
// activation constants pre-folded into weights. e.x = src col, e.y = weight bits.
__device__ int2 g_eh[EH_CAP];
__device__ int2 g_eo[EO_CAP];
__device__ int  g_hptr[NHID + 1];
__device__ int  g_optr[NOUT + 1];
// seg[4n+g] = start of group g of node n; seg[4N] = E sentinel.
__device__ __align__(16) int g_hseg[4 * NHID + 4];
__device__ __align__(16) int g_oseg[4 * NOUT + 4];

// ---------------- fast math ----------------
__device__ __forceinline__ float ex2f(float x) {
    float r; asm("ex2.approx.ftz.f32 %0, %1;" : "=f"(r) : "f"(x)); return r;
}
__device__ __forceinline__ float rcpf(float x) {
    float r; asm("rcp.approx.ftz.f32 %0, %1;" : "=f"(r) : "f"(x)); return r;
}
__device__ __forceinline__ float tanh_from_t(float t) {   // t = 2*log2e*z
    float e = ex2f(fminf(t, 126.f));
    return (e - 1.f) * rcpf(e + 1.f);
}

// ---------------- prep A: edge-parallel CSR row pointers --------------------
__global__ void prep_ptr_kernel(const int* __restrict__ rows_h,
                                const int* __restrict__ rows_o,
                                int Eh, int Eo) {
    int t = blockIdx.x * blockDim.x + threadIdx.x;
    if (t < Eh) {
        int r  = rows_h[t];
        int rp = (t == 0) ? -1 : rows_h[t - 1];
        for (int q = rp + 1; q <= r; q++) g_hptr[q] = t;
    } else if (t == Eh) {
        int rp = (Eh > 0) ? rows_h[Eh - 1] : -1;
        for (int q = rp + 1; q <= NHID; q++) g_hptr[q] = Eh;
    }
    int u = t - (Eh + 1);
    if (u >= 0 && u < Eo) {
        int r  = rows_o[u];
        int rp = (u == 0) ? -1 : rows_o[u - 1];
        for (int q = rp + 1; q <= r; q++) g_optr[q] = u;
    } else if (u == Eo) {
        int rp = (Eo > 0) ? rows_o[Eo - 1] : -1;
        for (int q = rp + 1; q <= NOUT; q++) g_optr[q] = Eo;
    }
}

// ---------------- prep B: warp-per-node act grouping (ballot prefix) --------
// Group order: g0=act1(linear), g1=act3(relu), g2=act2(tanh, w*=2log2e),
// g3=act4(sigmoid, w*=-log2e). 24 blocks x 16 warps = 384 nodes.
__global__ void prep_group_kernel(const float* __restrict__ wh, const float* __restrict__ wo,
                                  const int* __restrict__ cols_h, const int* __restrict__ acts_h,
                                  const int* __restrict__ cols_o, const int* __restrict__ acts_o,
                                  int Eh, int Eo) {
    int node = blockIdx.x * 16 + (threadIdx.x >> 5);
    int lane = threadIdx.x & 31;
    bool hid = node < NHID;
    int  n   = hid ? node : node - NHID;

    const int*   ptr  = hid ? g_hptr : g_optr;
    const int*   cols = hid ? cols_h : cols_o;
    const int*   acts = hid ? acts_h : acts_o;
    const float* wsrc = hid ? wh : wo;
    int2*        dst  = hid ? g_eh : g_eo;
    int*         seg  = hid ? g_hseg : g_oseg;

    int b0 = ptr[n], b1 = ptr[n + 1];

    // pass 1: per-group counts
    int c0 = 0, c1 = 0, c2 = 0, c3 = 0;
    for (int base = b0; base < b1; base += 32) {
        int i = base + lane;
        int a = (i < b1) ? acts[i] : -1;
        c0 += __popc(__ballot_sync(0xFFFFFFFFu, a == 1));
        c1 += __popc(__ballot_sync(0xFFFFFFFFu, a == 3));
        c2 += __popc(__ballot_sync(0xFFFFFFFFu, a == 2));
        c3 += __popc(__ballot_sync(0xFFFFFFFFu, a == 4));
    }
    int s0 = b0, s1 = s0 + c0, s2 = s1 + c1, s3 = s2 + c2;
    if (lane == 0) {
        seg[4 * n + 0] = s0; seg[4 * n + 1] = s1;
        seg[4 * n + 2] = s2; seg[4 * n + 3] = s3;
    }
    if (node == 0 && lane == 0)   g_hseg[4 * NHID] = Eh;
    if (node == NHID && lane == 0) g_oseg[4 * NOUT] = Eo;

    // pass 2: scatter with warp prefix
    int o0 = s0, o1 = s1, o2 = s2, o3 = s3;
    for (int base = b0; base < b1; base += 32) {
        int i = base + lane;
        int   a  = (i < b1) ? acts[i] : -1;
        int   cv = (i < b1) ? cols[i] : 0;
        float wv = (i < b1) ? wsrc[i] : 0.f;
        unsigned m0 = __ballot_sync(0xFFFFFFFFu, a == 1);
        unsigned m1 = __ballot_sync(0xFFFFFFFFu, a == 3);
        unsigned m2 = __ballot_sync(0xFFFFFFFFu, a == 2);
        unsigned m3 = __ballot_sync(0xFFFFFFFFu, a == 4);
        unsigned below = (1u << lane) - 1u;
        if (a == 1)      dst[o0 + __popc(m0 & below)] = make_int2(cv, __float_as_int(wv));
        else if (a == 3) dst[o1 + __popc(m1 & below)] = make_int2(cv, __float_as_int(wv));
        else if (a == 2) dst[o2 + __popc(m2 & below)] = make_int2(cv, __float_as_int(wv * 2.885390082f));
        else if (a == 4) dst[o3 + __popc(m3 & below)] = make_int2(cv, __float_as_int(wv * -1.442695041f));
        o0 += __popc(m0); o1 += __popc(m1); o2 += __popc(m2); o3 += __popc(m3);
    }
}

// ---------------- dual-row accumulation over act-sorted segments ------------
__device__ __forceinline__ float2 node_accum2(const float* __restrict__ r0,
                                              const float* __restrict__ r1,
                                              const int2* __restrict__ edges,
                                              int p0, int p1, int p2, int p3, int p4) {
    float a = 0.f, b = 0.f;
    #pragma unroll 2
    for (int i = p0; i < p1; i++) {                       // linear
        int2 e = __ldg(&edges[i]);
        float w = __int_as_float(e.y);
        a = fmaf(r0[e.x], w, a);
        b = fmaf(r1[e.x], w, b);
    }
    #pragma unroll 2
    for (int i = p1; i < p2; i++) {                       // relu
        int2 e = __ldg(&edges[i]);
        float w = __int_as_float(e.y);
        a += fmaxf(r0[e.x] * w, 0.f);
        b += fmaxf(r1[e.x] * w, 0.f);
    }
    #pragma unroll 2
    for (int i = p2; i < p3; i++) {                       // tanh (w pre-scaled 2log2e)
        int2 e = __ldg(&edges[i]);
        float w = __int_as_float(e.y);
        float ea = ex2f(fminf(r0[e.x] * w, 126.f));
        float eb = ex2f(fminf(r1[e.x] * w, 126.f));
        a += (ea - 1.f) * rcpf(ea + 1.f);
        b += (eb - 1.f) * rcpf(eb + 1.f);
    }
    #pragma unroll 2
    for (int i = p3; i < p4; i++) {                       // sigmoid (w pre-scaled -log2e)
        int2 e = __ldg(&edges[i]);
        float w = __int_as_float(e.y);
        a += rcpf(1.f + ex2f(r0[e.x] * w));
        b += rcpf(1.f + ex2f(r1[e.x] * w));
    }
    return make_float2(a, b);
}

// ---------------- main kernel ----------------
__global__ __launch_bounds__(NTHREADS, 1)
void wann_kernel(const float* __restrict__ x, float* __restrict__ out) {
    extern __shared__ float sm[];
    float* lb = sm;                         // [TB][LB_STRIDE]: x | H per row

    const int tid  = threadIdx.x;
    const int warp = tid >> 5;
    const int lane = tid & 31;
    const int row0 = blockIdx.x * TB;

    // Phase 0: stage x tile (64 rows x 128 float4 = 8192 float4, 8 iters)
    {
        const float4* x4 = (const float4*)(x + (size_t)row0 * IN_DIM);
        #pragma unroll
        for (int i = 0; i < (TB * IN_DIM / 4) / NTHREADS; i++) {
            int t  = tid + i * NTHREADS;
            int r  = t >> 7;
            int c4 = t & 127;
            float4 v = x4[r * 128 + c4];
            float* d = lb + r * LB_STRIDE + c4 * 4;
            d[0] = v.x; d[1] = v.y; d[2] = v.z; d[3] = v.w;
        }
    }
    __syncthreads();

    float* r0 = lb + lane * LB_STRIDE;              // batch row lane
    float* r1 = lb + (lane + 32) * LB_STRIDE;       // batch row lane+32

    // Phase 1: hidden nodes (warp -> node, thread -> 2 rows)
    #pragma unroll
    for (int j = 0; j < NHID / NWARPS; j++) {
        int h = warp + j * NWARPS;
        int4 s = *(const int4*)&g_hseg[4 * h];
        int  s4 = g_hseg[4 * h + 4];
        float2 v = node_accum2(r0, r1, g_eh, s.x, s.y, s.z, s.w, s4);
        r0[IN_DIM + h] = v.x;
        r1[IN_DIM + h] = v.y;
    }
    __syncthreads();

    // Phase 2: output nodes -> registers (8 per thread per row)
    float v0[NOUT / NWARPS], v1[NOUT / NWARPS];
    #pragma unroll
    for (int j = 0; j < NOUT / NWARPS; j++) {
        int o = warp + j * NWARPS;
        int4 s = *(const int4*)&g_oseg[4 * o];
        int  s4 = g_oseg[4 * o + 4];
        float2 acc = node_accum2(r0, r1, g_eo, s.x, s.y, s.z, s.w, s4);
        v0[j] = tanh_from_t(2.885390082f * acc.x);
        v1[j] = tanh_from_t(2.885390082f * acc.y);
    }
    __syncthreads();    // all lb reads done -> reuse as out staging

    // Phase 3a: stage outputs [TB][OS_STRIDE]
    #pragma unroll
    for (int j = 0; j < NOUT / NWARPS; j++) {
        int o = warp + j * NWARPS;
        lb[lane * OS_STRIDE + o]        = v0[j];
        lb[(lane + 32) * OS_STRIDE + o] = v1[j];
    }
    __syncthreads();

    // Phase 3b: coalesced flush (64*256 = 16384 floats, 16 iters)
    {
        float* orow = out + (size_t)row0 * NOUT;
        #pragma unroll
        for (int i = 0; i < (TB * NOUT) / NTHREADS; i++) {
            int t = tid + i * NTHREADS;
            int r = t >> 8;
            int c = t & 255;
            orow[r * NOUT + c] = lb[r * OS_STRIDE + c];
        }
    }
}

// ---------------- launch ----------------
extern "C" void kernel_launch(void* const* d_in, const int* in_sizes, int n_in,
                              void* d_out, int out_size) {
    const float* x      = (const float*)d_in[0];
    const float* wh     = (const float*)d_in[1];
    const float* wo     = (const float*)d_in[2];
    const int*   rows_h = (const int*)d_in[3];
    const int*   cols_h = (const int*)d_in[4];
    const int*   acts_h = (const int*)d_in[5];
    const int*   rows_o = (const int*)d_in[6];
    const int*   cols_o = (const int*)d_in[7];
    const int*   acts_o = (const int*)d_in[8];
    float*       out    = (float*)d_out;

    int Eh = in_sizes[1]; if (Eh > EH_CAP) Eh = EH_CAP;
    int Eo = in_sizes[2]; if (Eo > EO_CAP) Eo = EO_CAP;

    int nptr = Eh + Eo + 2;
    prep_ptr_kernel<<<(nptr + 511) / 512, 512>>>(rows_h, rows_o, Eh, Eo);
    prep_group_kernel<<<(NHID + NOUT) / 16, 512>>>(wh, wo, cols_h, acts_h,
                                                   cols_o, acts_o, Eh, Eo);

    size_t smem = (size_t)(TB * LB_STRIDE) * sizeof(float);   // 164 KB
    cudaFuncSetAttribute(wann_kernel, cudaFuncAttributeMaxDynamicSharedMemorySize, (int)smem);
    wann_kernel<<<BTOT / TB, NTHREADS, smem>>>(x, out);
}

// round 14
// speedup vs baseline: 2.1609x; 1.6420x over previous
#include <cuda_runtime.h>
#include <stdint.h>

// Static graph dims
#define BTOT     16384
#define IN_DIM   512
#define NHID     128
#define NOUT     256
#define TB       64          // batch rows per block; thread handles rows lane, lane+32
#define NTHREADS 1024
#define NWARPS   32

#define LB_STRIDE 641        // 512 x + 128 H + 1 pad (odd -> conflict-free)
#define OS_STRIDE 257

#define EH_CAP 4096
#define EO_CAP 8192
#define MAXSZ  64            // degree histogram cap for assignment sort

// Combined edge table: hidden edges [0,Eh), output edges [Eh, Eh+Eo).
// Grouped per node in order [linear, relu, tanh(w*=2log2e), sigmoid(w*=-log2e)].
__device__ int2 g_edges[EH_CAP + EO_CAP];
// seg[4n+g] = start of group g of node n (output segs offset by Eh); seg[4N] sentinel.
__device__ __align__(16) int g_hseg[4 * NHID + 4];
__device__ __align__(16) int g_oseg[4 * NOUT + 4];
// Edge-balanced node->warp assignment: warp w slot j -> node
__device__ int g_hassign[NHID];     // [32][NHID/32]
__device__ int g_oassign[NOUT];     // [32][NOUT/32]

// Smem layout offsets (bytes)
#define SM_LB     0
#define SM_HSEG   (TB * LB_STRIDE * 4)                 // 164096
#define SM_OSEG   (SM_HSEG + (4 * NHID + 4) * 4)       // +2064
#define SM_HASN   (SM_OSEG + (4 * NOUT + 4) * 4)       // +4112
#define SM_OASN   (SM_HASN + NHID * 4)
#define SM_EDGES  (SM_OASN + NOUT * 4)                 // 8-byte aligned

// ---------------- fast math ----------------
__device__ __forceinline__ float ex2f(float x) {
    float r; asm("ex2.approx.ftz.f32 %0, %1;" : "=f"(r) : "f"(x)); return r;
}
__device__ __forceinline__ float rcpf(float x) {
    float r; asm("rcp.approx.ftz.f32 %0, %1;" : "=f"(r) : "f"(x)); return r;
}
__device__ __forceinline__ float tanh_from_t(float t) {   // t = 2*log2e*z
    float e = ex2f(fminf(t, 126.f));
    return (e - 1.f) * rcpf(e + 1.f);
}

// ---------------- warp-cooperative 32-ary lower_bound -----------------------
__device__ __forceinline__ int warp_lb(const int* __restrict__ a, int E, int v) {
    const unsigned FULL = 0xFFFFFFFFu;
    int lane = threadIdx.x & 31;
    int lo = 0, hi = E;                       // answer in [lo, hi]
    while (hi - lo > 31) {
        int len = hi - lo;
        int idx = lo + (int)(((long long)(lane + 1) * len) / 33);
        int lt = (a[idx] < v) ? 1 : 0;
        unsigned m = __ballot_sync(FULL, lt);
        int cnt = __popc(m);                  // lt is a prefix (a sorted)
        int nlo = (cnt == 0)  ? lo : lo + (int)(((long long)cnt * len) / 33) + 1;
        int nhi = (cnt == 32) ? hi : lo + (int)(((long long)(cnt + 1) * len) / 33);
        lo = nlo; hi = nhi;
    }
    int idx = lo + lane;
    int ge = (idx < hi) ? (a[idx] >= v ? 1 : 0) : 1;
    unsigned m = __ballot_sync(FULL, ge);
    return lo + (__ffs(m) - 1);
}

// ---------------- prep: warp-per-node CSR + act grouping --------------------
__global__ void prep_kernel(const float* __restrict__ wh, const float* __restrict__ wo,
                            const int* __restrict__ rows_h, const int* __restrict__ cols_h,
                            const int* __restrict__ acts_h,
                            const int* __restrict__ rows_o, const int* __restrict__ cols_o,
                            const int* __restrict__ acts_o,
                            int Eh, int Eo) {
    int node = blockIdx.x * 16 + (threadIdx.x >> 5);
    int lane = threadIdx.x & 31;
    bool hid = node < NHID;
    int  n   = hid ? node : node - NHID;

    const int*   rows = hid ? rows_h : rows_o;
    const int*   cols = hid ? cols_h : cols_o;
    const int*   acts = hid ? acts_h : acts_o;
    const float* wsrc = hid ? wh : wo;
    int          E    = hid ? Eh : Eo;
    int          off  = hid ? 0 : Eh;        // output edges after hidden in g_edges
    int*         seg  = hid ? g_hseg : g_oseg;

    int b0 = warp_lb(rows, E, n);
    int b1 = warp_lb(rows, E, n + 1);

    // pass 1: per-group counts
    int c0 = 0, c1 = 0, c2 = 0, c3 = 0;
    for (int base = b0; base < b1; base += 32) {
        int i = base + lane;
        int a = (i < b1) ? acts[i] : -1;
        c0 += __popc(__ballot_sync(0xFFFFFFFFu, a == 1));
        c1 += __popc(__ballot_sync(0xFFFFFFFFu, a == 3));
        c2 += __popc(__ballot_sync(0xFFFFFFFFu, a == 2));
        c3 += __popc(__ballot_sync(0xFFFFFFFFu, a == 4));
    }
    int s0 = off + b0, s1 = s0 + c0, s2 = s1 + c1, s3 = s2 + c2;
    if (lane == 0) {
        seg[4 * n + 0] = s0; seg[4 * n + 1] = s1;
        seg[4 * n + 2] = s2; seg[4 * n + 3] = s3;
    }
    if (node == 0 && lane == 0)    g_hseg[4 * NHID] = Eh;
    if (node == NHID && lane == 0) g_oseg[4 * NOUT] = Eh + Eo;

    // pass 2: scatter with warp prefix, folding act constants into weights
    int o0 = s0, o1 = s1, o2 = s2, o3 = s3;
    for (int base = b0; base < b1; base += 32) {
        int i = base + lane;
        int   a  = (i < b1) ? acts[i] : -1;
        int   cv = (i < b1) ? cols[i] : 0;
        float wv = (i < b1) ? wsrc[i] : 0.f;
        unsigned m0 = __ballot_sync(0xFFFFFFFFu, a == 1);
        unsigned m1 = __ballot_sync(0xFFFFFFFFu, a == 3);
        unsigned m2 = __ballot_sync(0xFFFFFFFFu, a == 2);
        unsigned m3 = __ballot_sync(0xFFFFFFFFu, a == 4);
        unsigned below = (1u << lane) - 1u;
        if (a == 1)      g_edges[o0 + __popc(m0 & below)] = make_int2(cv, __float_as_int(wv));
        else if (a == 3) g_edges[o1 + __popc(m1 & below)] = make_int2(cv, __float_as_int(wv));
        else if (a == 2) g_edges[o2 + __popc(m2 & below)] = make_int2(cv, __float_as_int(wv * 2.885390082f));
        else if (a == 4) g_edges[o3 + __popc(m3 & below)] = make_int2(cv, __float_as_int(wv * -1.442695041f));
        o0 += __popc(m0); o1 += __popc(m1); o2 += __popc(m2); o3 += __popc(m3);
    }
}

// ---------------- assign: edge-balanced node->warp mapping ------------------
// Counting-sort nodes by degree (desc), boustrophedon across 32 warps.
// Same-degree ties resolved by atomics (nondeterministic order), but node
// results are position-fixed, so output values are unaffected.
__global__ void assign_kernel() {
    __shared__ int base[MAXSZ];
    __shared__ int cur[MAXSZ];
    int t = threadIdx.x;

    // ---- hidden set ----
    if (t < MAXSZ) cur[t] = 0;
    __syncthreads();
    int hsz = 0;
    if (t < NHID) {
        hsz = min(g_hseg[4 * t + 4] - g_hseg[4 * t], MAXSZ - 1);
        atomicAdd(&cur[hsz], 1);
    }
    __syncthreads();
    if (t == 0) {
        int acc = 0;
        for (int s = MAXSZ - 1; s >= 0; s--) { base[s] = acc; acc += cur[s]; }
    }
    __syncthreads();
    if (t < MAXSZ) cur[t] = 0;
    __syncthreads();
    if (t < NHID) {
        int r = base[hsz] + atomicAdd(&cur[hsz], 1);
        int row = r >> 5, col = r & 31;
        int w = (row & 1) ? (31 - col) : col;
        g_hassign[w * (NHID / 32) + row] = t;
    }
    __syncthreads();

    // ---- output set ----
    if (t < MAXSZ) cur[t] = 0;
    __syncthreads();
    int osz = 0;
    if (t < NOUT) {
        osz = min(g_oseg[4 * t + 4] - g_oseg[4 * t], MAXSZ - 1);
        atomicAdd(&cur[osz], 1);
    }
    __syncthreads();
    if (t == 0) {
        int acc = 0;
        for (int s = MAXSZ - 1; s >= 0; s--) { base[s] = acc; acc += cur[s]; }
    }
    __syncthreads();
    if (t < MAXSZ) cur[t] = 0;
    __syncthreads();
    if (t < NOUT) {
        int r = base[osz] + atomicAdd(&cur[osz], 1);
        int row = r >> 5, col = r & 31;
        int w = (row & 1) ? (31 - col) : col;
        g_oassign[w * (NOUT / 32) + row] = t;
    }
}

// ---------------- dual-row accumulation over act-sorted segments ------------
__device__ __forceinline__ float2 node_accum2(const float* __restrict__ r0,
                                              const float* __restrict__ r1,
                                              const int2* __restrict__ edges,
                                              int p0, int p1, int p2, int p3, int p4) {
    float a = 0.f, b = 0.f;
    #pragma unroll 2
    for (int i = p0; i < p1; i++) {                       // linear
        int2 e = edges[i];
        float w = __int_as_float(e.y);
        a = fmaf(r0[e.x], w, a);
        b = fmaf(r1[e.x], w, b);
    }
    #pragma unroll 2
    for (int i = p1; i < p2; i++) {                       // relu
        int2 e = edges[i];
        float w = __int_as_float(e.y);
        a += fmaxf(r0[e.x] * w, 0.f);
        b += fmaxf(r1[e.x] * w, 0.f);
    }
    #pragma unroll 2
    for (int i = p2; i < p3; i++) {                       // tanh (w pre-scaled 2log2e)
        int2 e = edges[i];
        float w = __int_as_float(e.y);
        float ea = ex2f(fminf(r0[e.x] * w, 126.f));
        float eb = ex2f(fminf(r1[e.x] * w, 126.f));
        a += (ea - 1.f) * rcpf(ea + 1.f);
        b += (eb - 1.f) * rcpf(eb + 1.f);
    }
    #pragma unroll 2
    for (int i = p3; i < p4; i++) {                       // sigmoid (w pre-scaled -log2e)
        int2 e = edges[i];
        float w = __int_as_float(e.y);
        a += rcpf(1.f + ex2f(r0[e.x] * w));
        b += rcpf(1.f + ex2f(r1[e.x] * w));
    }
    return make_float2(a, b);
}

// ---------------- main kernel ----------------
__global__ __launch_bounds__(NTHREADS, 1)
void wann_kernel(const float* __restrict__ x, float* __restrict__ out,
                 int Eh, int Eo) {
    extern __shared__ char smraw[];
    float* lb      = (float*)(smraw + SM_LB);            // [TB][LB_STRIDE]
    int*   s_hseg  = (int*)  (smraw + SM_HSEG);
    int*   s_oseg  = (int*)  (smraw + SM_OSEG);
    int*   s_hasn  = (int*)  (smraw + SM_HASN);
    int*   s_oasn  = (int*)  (smraw + SM_OASN);
    int2*  se      = (int2*) (smraw + SM_EDGES);

    const int tid  = threadIdx.x;
    const int warp = tid >> 5;
    const int lane = tid & 31;
    const int row0 = blockIdx.x * TB;
    const int Etot = Eh + Eo;

    // Phase 0a: copy metadata + edges into smem
    for (int i = tid; i < 4 * NHID + 4; i += NTHREADS) s_hseg[i] = g_hseg[i];
    for (int i = tid; i < 4 * NOUT + 4; i += NTHREADS) s_oseg[i] = g_oseg[i];
    for (int i = tid; i < NHID; i += NTHREADS) s_hasn[i] = g_hassign[i];
    for (int i = tid; i < NOUT; i += NTHREADS) s_oasn[i] = g_oassign[i];
    for (int i = tid; i < Etot; i += NTHREADS) se[i] = g_edges[i];

    // Phase 0b: stage x tile (64 rows x 128 float4)
    {
        const float4* x4 = (const float4*)(x + (size_t)row0 * IN_DIM);
        #pragma unroll
        for (int i = 0; i < (TB * IN_DIM / 4) / NTHREADS; i++) {
            int t  = tid + i * NTHREADS;
            int r  = t >> 7;
            int c4 = t & 127;
            float4 v = x4[r * 128 + c4];
            float* d = lb + r * LB_STRIDE + c4 * 4;
            d[0] = v.x; d[1] = v.y; d[2] = v.z; d[3] = v.w;
        }
    }
    __syncthreads();

    float* r0 = lb + lane * LB_STRIDE;
    float* r1 = lb + (lane + 32) * LB_STRIDE;

    // Phase 1: hidden nodes, edge-balanced assignment
    #pragma unroll
    for (int j = 0; j < NHID / NWARPS; j++) {
        int h = s_hasn[warp * (NHID / NWARPS) + j];
        int4 s = *(const int4*)&s_hseg[4 * h];
        int  s4 = s_hseg[4 * h + 4];
        float2 v = node_accum2(r0, r1, se, s.x, s.y, s.z, s.w, s4);
        r0[IN_DIM + h] = v.x;
        r1[IN_DIM + h] = v.y;
    }
    __syncthreads();

    // Phase 2: output nodes, edge-balanced; results buffered in registers
    float v0[NOUT / NWARPS], v1[NOUT / NWARPS];
    int   oid[NOUT / NWARPS];
    #pragma unroll
    for (int j = 0; j < NOUT / NWARPS; j++) {
        int o = s_oasn[warp * (NOUT / NWARPS) + j];
        oid[j] = o;
        int4 s = *(const int4*)&s_oseg[4 * o];
        int  s4 = s_oseg[4 * o + 4];
        float2 acc = node_accum2(r0, r1, se, s.x, s.y, s.z, s.w, s4);
        v0[j] = tanh_from_t(2.885390082f * acc.x);
        v1[j] = tanh_from_t(2.885390082f * acc.y);
    }
    __syncthreads();    // all lb reads done -> reuse as out staging

    // Phase 3a: stage outputs [TB][OS_STRIDE]
    #pragma unroll
    for (int j = 0; j < NOUT / NWARPS; j++) {
        int o = oid[j];
        lb[lane * OS_STRIDE + o]        = v0[j];
        lb[(lane + 32) * OS_STRIDE + o] = v1[j];
    }
    __syncthreads();

    // Phase 3b: coalesced flush
    {
        float* orow = out + (size_t)row0 * NOUT;
        #pragma unroll
        for (int i = 0; i < (TB * NOUT) / NTHREADS; i++) {
            int t = tid + i * NTHREADS;
            int r = t >> 8;
            int c = t & 255;
            orow[r * NOUT + c] = lb[r * OS_STRIDE + c];
        }
    }
}

// ---------------- launch ----------------
extern "C" void kernel_launch(void* const* d_in, const int* in_sizes, int n_in,
                              void* d_out, int out_size) {
    const float* x      = (const float*)d_in[0];
    const float* wh     = (const float*)d_in[1];
    const float* wo     = (const float*)d_in[2];
    const int*   rows_h = (const int*)d_in[3];
    const int*   cols_h = (const int*)d_in[4];
    const int*   acts_h = (const int*)d_in[5];
    const int*   rows_o = (const int*)d_in[6];
    const int*   cols_o = (const int*)d_in[7];
    const int*   acts_o = (const int*)d_in[8];
    float*       out    = (float*)d_out;

    int Eh = in_sizes[1]; if (Eh > EH_CAP) Eh = EH_CAP;
    int Eo = in_sizes[2]; if (Eo > EO_CAP) Eo = EO_CAP;

    prep_kernel<<<(NHID + NOUT) / 16, 512>>>(wh, wo, rows_h, cols_h, acts_h,
                                             rows_o, cols_o, acts_o, Eh, Eo);
    assign_kernel<<<1, 512>>>();

    size_t smem = (size_t)SM_EDGES + (size_t)(Eh + Eo) * sizeof(int2);
    cudaFuncSetAttribute(wann_kernel, cudaFuncAttributeMaxDynamicSharedMemorySize, (int)smem);
    wann_kernel<<<BTOT / TB, NTHREADS, smem>>>(x, out, Eh, Eo);
}